// round 8
// baseline (speedup 1.0000x reference)
#include <cuda_runtime.h>
#include <math.h>

#define SEQ   2048
#define NHIST 4096
#define TGT   1024
#define DL    256
#define DT    32
#define DU    64
#define HDIM  256
#define INDIM 288
#define NLOC  100000
#define FEATD 1088

typedef unsigned long long ull;

// ---------------- static scratch ----------------
__device__ float g_x     [SEQ * INDIM];
__device__ float g_xr    [SEQ * INDIM];
__device__ float g_gi_f  [SEQ * 3 * HDIM];
__device__ float g_gi_b  [TGT * 3 * HDIM];
__device__ float g_hs_f  [SEQ * HDIM];
__device__ float g_hs_b  [SEQ * HDIM];
__device__ float g_histin[NHIST * INDIM];
__device__ float g_hist  [NHIST * 2 * HDIM];
__device__ float g_scores[TGT * NHIST];
__device__ float g_q     [TGT * 2 * HDIM];
__device__ float g_ctx   [TGT * 2 * HDIM];
__device__ float g_feat  [TGT * FEATD];
__device__ int   g_offs  [NHIST];

// ---------------- helpers ----------------
__device__ __forceinline__ ull pk2(float lo, float hi) {
    ull r; asm("mov.b64 %0, {%1, %2};" : "=l"(r) : "f"(lo), "f"(hi)); return r;
}
__device__ __forceinline__ void unpk(ull v, float &a, float &b) {
    asm("mov.b64 {%0, %1}, %2;" : "=f"(a), "=f"(b) : "l"(v));
}
__device__ __forceinline__ void fma2(ull &c, ull a, ull b) {
    asm("fma.rn.f32x2 %0, %1, %2, %0;" : "+l"(c) : "l"(a), "l"(b));
}
__device__ __forceinline__ void cluster_sync_() {
    asm volatile("barrier.cluster.arrive.aligned;\n\t"
                 "barrier.cluster.wait.aligned;" ::: "memory");
}
__device__ __forceinline__ void st_cluster_f32(float* p, unsigned rank, float v) {
    unsigned a = (unsigned)__cvta_generic_to_shared(p), ra;
    asm volatile("mapa.shared::cluster.u32 %0, %1, %2;" : "=r"(ra) : "r"(a), "r"(rank));
    asm volatile("st.shared::cluster.u32 [%0], %1;" :: "r"(ra), "r"(__float_as_uint(v)) : "memory");
}
__device__ __forceinline__ float sigmoidf_(float x) { return 1.0f / (1.0f + expf(-x)); }

// ---------------- gathers ----------------
__global__ void k_gather(const int* __restrict__ loc, const int* __restrict__ tim,
                         const float* __restrict__ emb_loc, const float* __restrict__ emb_tim) {
    int t = blockIdx.x, c = threadIdx.x;
    float v = (c < DL) ? emb_loc[(size_t)loc[t] * DL + c]
                       : emb_tim[(size_t)tim[t] * DT + (c - DL)];
    g_x [(size_t)t * INDIM + c] = v;
    g_xr[(size_t)(SEQ - 1 - t) * INDIM + c] = v;
}

__global__ __launch_bounds__(1024) void k_scan(const int* __restrict__ counts) {
    __shared__ int s[1024];
    int tid = threadIdx.x;
    int v0 = counts[4*tid], v1 = counts[4*tid+1], v2 = counts[4*tid+2], v3 = counts[4*tid+3];
    int locsum = v0 + v1 + v2 + v3;
    s[tid] = locsum; __syncthreads();
    for (int ofs = 1; ofs < 1024; ofs <<= 1) {
        int t_ = 0; if (tid >= ofs) t_ = s[tid - ofs];
        __syncthreads();
        s[tid] += t_;
        __syncthreads();
    }
    int ex = s[tid] - locsum;
    g_offs[4*tid] = ex;  g_offs[4*tid+1] = ex + v0;
    g_offs[4*tid+2] = ex + v0 + v1;  g_offs[4*tid+3] = ex + v0 + v1 + v2;
}

__global__ void k_hist(const int* __restrict__ hloc, const int* __restrict__ htim,
                       const int* __restrict__ counts,
                       const float* __restrict__ emb_loc, const float* __restrict__ emb_tim) {
    int i = blockIdx.x, c = threadIdx.x;
    int off = g_offs[i], cnt = counts[i];
    float v;
    if (c < DL) {
        float acc = 0.f;
        for (int k = 0; k < cnt; k++) acc += emb_loc[(size_t)hloc[off + k] * DL + c];
        v = acc / (float)cnt;
    } else {
        v = emb_tim[(size_t)htim[off] * DT + (c - DL)];
    }
    g_histin[(size_t)i * INDIM + c] = v;
}

__global__ void k_build_q() {
    int b = blockIdx.x, c = threadIdx.x;
    float v = (c < HDIM) ? g_hs_f[(size_t)(SEQ - TGT + b) * HDIM + c]
                         : g_hs_b[(size_t)(SEQ - TGT + b) * HDIM + (c - HDIM)];
    g_q[(size_t)b * (2*HDIM) + c] = v;
}

__global__ void k_feat(const int* __restrict__ uid, const float* __restrict__ emb_uid) {
    int b = blockIdx.x; int u = uid[0];
    for (int c = threadIdx.x; c < FEATD; c += blockDim.x) {
        float v;
        if (c < 2*HDIM)      v = g_q  [(size_t)b * (2*HDIM) + c];
        else if (c < 4*HDIM) v = g_ctx[(size_t)b * (2*HDIM) + (c - 2*HDIM)];
        else                 v = emb_uid[(size_t)u * DU + (c - 4*HDIM)];
        g_feat[(size_t)b * FEATD + c] = v;
    }
}

// ---------------- row softmax / log-softmax ----------------
__global__ __launch_bounds__(256) void k_softmax_rows() {
    int row = blockIdx.x, tid = threadIdx.x;
    float* p = g_scores + (size_t)row * NHIST;
    __shared__ float red[256];
    float m = -1e30f;
    for (int i = tid; i < NHIST; i += 256) m = fmaxf(m, p[i]);
    red[tid] = m; __syncthreads();
    for (int s = 128; s > 0; s >>= 1) { if (tid < s) red[tid] = fmaxf(red[tid], red[tid+s]); __syncthreads(); }
    m = red[0]; __syncthreads();
    float sum = 0.f;
    for (int i = tid; i < NHIST; i += 256) { float e = __expf(p[i] - m); p[i] = e; sum += e; }
    red[tid] = sum; __syncthreads();
    for (int s = 128; s > 0; s >>= 1) { if (tid < s) red[tid] += red[tid+s]; __syncthreads(); }
    float inv = 1.f / red[0];
    for (int i = tid; i < NHIST; i += 256) p[i] *= inv;
}

__global__ __launch_bounds__(256) void k_logsoftmax(float* __restrict__ out) {
    int row = blockIdx.x, tid = threadIdx.x;
    float* p = out + (size_t)row * NLOC;
    __shared__ float red[256];
    float m = -1e30f;
    for (int i = tid; i < NLOC; i += 256) m = fmaxf(m, p[i]);
    red[tid] = m; __syncthreads();
    for (int s = 128; s > 0; s >>= 1) { if (tid < s) red[tid] = fmaxf(red[tid], red[tid+s]); __syncthreads(); }
    m = red[0]; __syncthreads();
    float sum = 0.f;
    for (int i = tid; i < NLOC; i += 256) sum += __expf(p[i] - m);
    red[tid] = sum; __syncthreads();
    for (int s = 128; s > 0; s >>= 1) { if (tid < s) red[tid] += red[tid+s]; __syncthreads(); }
    float lse = m + logf(red[0]);
    for (int i = tid; i < NLOC; i += 256) p[i] -= lse;
}

// ---------------- SGEMM: C = act(A @ op(B) + bias) ----------------
// BL=0: B (N,K) row-major (NT).  BL=1: B (K,N) row-major (NN).  ACT=1: tanh.
// Requires K%16==0, and alignment K%4==0, N%4==0.
template<int BL, int ACT>
__global__ __launch_bounds__(256, 1) void sgemm_kernel(
    const float* __restrict__ A, const float* __restrict__ B,
    const float* __restrict__ bias, float* __restrict__ C,
    int M, int N, int K)
{
    __shared__ __align__(16) float As[16][128];
    __shared__ __align__(16) float Bs[16][128];
    const int bm = blockIdx.y * 128, bn = blockIdx.x * 128;
    const int tid = threadIdx.x;
    const int tx = tid & 15, ty = tid >> 4;

    ull acc[8][4];
#pragma unroll
    for (int i = 0; i < 8; i++)
#pragma unroll
        for (int j = 0; j < 4; j++) acc[i][j] = 0ull;

    for (int k0 = 0; k0 < K; k0 += 16) {
#pragma unroll
        for (int l = 0; l < 2; l++) {
            int r = (tid >> 2) + l * 64, kc = (tid & 3) * 4, gr = bm + r;
            float4 v = make_float4(0.f,0.f,0.f,0.f);
            if (gr < M) v = *(const float4*)(A + (size_t)gr * K + k0 + kc);
            As[kc][r]=v.x; As[kc+1][r]=v.y; As[kc+2][r]=v.z; As[kc+3][r]=v.w;
        }
        if (BL == 0) {
#pragma unroll
            for (int l = 0; l < 2; l++) {
                int r = (tid >> 2) + l * 64, kc = (tid & 3) * 4, gr = bn + r;
                float4 v = make_float4(0.f,0.f,0.f,0.f);
                if (gr < N) v = *(const float4*)(B + (size_t)gr * K + k0 + kc);
                Bs[kc][r]=v.x; Bs[kc+1][r]=v.y; Bs[kc+2][r]=v.z; Bs[kc+3][r]=v.w;
            }
        } else {
#pragma unroll
            for (int l = 0; l < 2; l++) {
                int kk = (tid >> 5) + l * 8, c = (tid & 31) * 4, gc = bn + c;
                float4 v = make_float4(0.f,0.f,0.f,0.f);
                if (gc < N) v = *(const float4*)(B + (size_t)(k0 + kk) * N + gc);
                *(float4*)&Bs[kk][c] = v;
            }
        }
        __syncthreads();
#pragma unroll
        for (int kk = 0; kk < 16; kk++) {
            float4 a0 = *(float4*)&As[kk][ty * 8];
            float4 a1 = *(float4*)&As[kk][ty * 8 + 4];
            ulonglong2 bp0 = *(ulonglong2*)&Bs[kk][tx * 8];
            ulonglong2 bp1 = *(ulonglong2*)&Bs[kk][tx * 8 + 4];
            float av[8] = {a0.x,a0.y,a0.z,a0.w,a1.x,a1.y,a1.z,a1.w};
#pragma unroll
            for (int i = 0; i < 8; i++) {
                ull aa = pk2(av[i], av[i]);
                fma2(acc[i][0], aa, bp0.x);
                fma2(acc[i][1], aa, bp0.y);
                fma2(acc[i][2], aa, bp1.x);
                fma2(acc[i][3], aa, bp1.y);
            }
        }
        __syncthreads();
    }
#pragma unroll
    for (int i = 0; i < 8; i++) {
        int gr = bm + ty * 8 + i;
        if (gr >= M) continue;
#pragma unroll
        for (int j = 0; j < 4; j++) {
            int gc = bn + tx * 8 + 2 * j;
            if (gc >= N) continue;
            float v0, v1; unpk(acc[i][j], v0, v1);
            if (bias) { v0 += bias[gc]; v1 += bias[gc + 1]; }
            if (ACT == 1) { v0 = tanhf(v0); v1 = tanhf(v1); }
            *(float2*)(C + (size_t)gr * N + gc) = make_float2(v0, v1);
        }
    }
}

// ---------------- GRU: cluster-of-8, register-resident Whh ----------------
// Grid 16 CTAs (2 clusters of 8). dir = blockIdx.x>>3 (0 fwd, 1 bwd).
// CTA rank owns h-dims [rank*32, rank*32+32) for all 3 gates: 96x256 weights
// in registers. 384 threads: rg=tid>>4 (24 groups of 4 rows), cg=tid&15.
__global__ __launch_bounds__(384, 1) __cluster_dims__(8, 1, 1)
void k_gru(const float* __restrict__ Whh_f, const float* __restrict__ Whh_b,
           const float* __restrict__ bhh_f, const float* __restrict__ bhh_b)
{
    __shared__ __align__(16) float hbuf[2][HDIM];
    __shared__ float gh[96];
    const int tid = threadIdx.x;
    unsigned rank; asm("mov.u32 %0, %%cluster_ctarank;" : "=r"(rank));
    const int dir = blockIdx.x >> 3;

    const float* Whh = dir ? Whh_b : Whh_f;
    const float* bhh = dir ? bhh_b : bhh_f;
    const float* gi  = dir ? g_gi_b : g_gi_f;
    float*       hs  = dir ? g_hs_b : g_hs_f;
    const int nsteps = dir ? TGT : SEQ;

    const int rg = tid >> 4, cg = tid & 15;

    ull w2[4][8];
#pragma unroll
    for (int rr = 0; rr < 4; rr++) {
        int lr = 4 * rg + rr;
        int R = (lr >> 5) * HDIM + (int)rank * 32 + (lr & 31);
        const float4* p = (const float4*)(Whh + (size_t)R * HDIM + cg * 16);
#pragma unroll
        for (int q = 0; q < 4; q++) {
            float4 v = p[q];
            w2[rr][2*q]   = pk2(v.x, v.y);
            w2[rr][2*q+1] = pk2(v.z, v.w);
        }
    }
    float bhr = 0.f, bhz = 0.f, bhn = 0.f;
    if (tid < 32) {
        int d = (int)rank * 32 + tid;
        bhr = bhh[d]; bhz = bhh[HDIM + d]; bhn = bhh[2*HDIM + d];
    }
    if (tid < HDIM) { hbuf[0][tid] = 0.f; }
    __syncthreads();
    cluster_sync_();

    int buf = 0;
    for (int t = 0; t < nsteps; t++) {
        float gir = 0.f, giz = 0.f, gin = 0.f;
        if (tid < 32) {
            size_t base = (size_t)t * (3 * HDIM) + rank * 32 + tid;
            gir = gi[base]; giz = gi[base + HDIM]; gin = gi[base + 2*HDIM];
        }
        const float* hb = hbuf[buf];
        ulonglong2 h01 = *(const ulonglong2*)(hb + cg * 16);
        ulonglong2 h23 = *(const ulonglong2*)(hb + cg * 16 + 4);
        ulonglong2 h45 = *(const ulonglong2*)(hb + cg * 16 + 8);
        ulonglong2 h67 = *(const ulonglong2*)(hb + cg * 16 + 12);
        ull hv[8] = {h01.x, h01.y, h23.x, h23.y, h45.x, h45.y, h67.x, h67.y};

        ull acc[4] = {0ull, 0ull, 0ull, 0ull};
#pragma unroll
        for (int rr = 0; rr < 4; rr++)
#pragma unroll
            for (int q = 0; q < 8; q++) fma2(acc[rr], w2[rr][q], hv[q]);

        float accf[4];
#pragma unroll
        for (int rr = 0; rr < 4; rr++) {
            float lo, hi; unpk(acc[rr], lo, hi);
            accf[rr] = lo + hi;
#pragma unroll
            for (int ofs = 8; ofs > 0; ofs >>= 1)
                accf[rr] += __shfl_xor_sync(0xffffffffu, accf[rr], ofs, 16);
        }
        if (cg == 0) {
#pragma unroll
            for (int rr = 0; rr < 4; rr++) gh[4 * rg + rr] = accf[rr];
        }
        __syncthreads();

        if (tid < 32) {
            float hprev = hbuf[buf][(int)rank * 32 + tid];
            float r = sigmoidf_(gir + gh[tid]       + bhr);
            float z = sigmoidf_(giz + gh[32 + tid]  + bhz);
            float n = tanhf    (gin + r * (gh[64 + tid] + bhn));
            float hn = (1.0f - z) * n + z * hprev;
            int d = (int)rank * 32 + tid;
#pragma unroll
            for (unsigned rk = 0; rk < 8; rk++)
                st_cluster_f32(&hbuf[buf ^ 1][d], rk, hn);
            size_t row = dir ? (size_t)(SEQ - 1 - t) : (size_t)t;
            hs[row * HDIM + d] = hn;
        }
        cluster_sync_();
        buf ^= 1;
    }
}

// ---------------- launch ----------------
extern "C" void kernel_launch(void* const* d_in, const int* in_sizes, int n_in,
                              void* d_out, int out_size) {
    const int*   loc     = (const int*)  d_in[0];
    const int*   tim     = (const int*)  d_in[1];
    const int*   hloc    = (const int*)  d_in[2];
    const int*   htim    = (const int*)  d_in[3];
    const int*   hcount  = (const int*)  d_in[4];
    const int*   uid     = (const int*)  d_in[5];
    // d_in[6] = target_len (compile-time TGT)
    const float* emb_loc = (const float*)d_in[7];
    const float* emb_tim = (const float*)d_in[8];
    const float* emb_uid = (const float*)d_in[9];
    const float* W_attn  = (const float*)d_in[10];
    const float* b_attn  = (const float*)d_in[11];
    const float* Wih_f   = (const float*)d_in[12];
    const float* Whh_f   = (const float*)d_in[13];
    const float* bih_f   = (const float*)d_in[14];
    const float* bhh_f   = (const float*)d_in[15];
    const float* Wih_b   = (const float*)d_in[16];
    const float* Whh_b   = (const float*)d_in[17];
    const float* bih_b   = (const float*)d_in[18];
    const float* bhh_b   = (const float*)d_in[19];
    const float* Wf      = (const float*)d_in[20];
    const float* bf      = (const float*)d_in[21];
    float* out = (float*)d_out;

    float *x, *xr, *gi_f, *gi_b, *histin, *hist, *scores, *q, *ctx, *feat;
    cudaGetSymbolAddress((void**)&x, g_x);
    cudaGetSymbolAddress((void**)&xr, g_xr);
    cudaGetSymbolAddress((void**)&gi_f, g_gi_f);
    cudaGetSymbolAddress((void**)&gi_b, g_gi_b);
    cudaGetSymbolAddress((void**)&histin, g_histin);
    cudaGetSymbolAddress((void**)&hist, g_hist);
    cudaGetSymbolAddress((void**)&scores, g_scores);
    cudaGetSymbolAddress((void**)&q, g_q);
    cudaGetSymbolAddress((void**)&ctx, g_ctx);
    cudaGetSymbolAddress((void**)&feat, g_feat);

    k_gather<<<SEQ, INDIM>>>(loc, tim, emb_loc, emb_tim);
    k_scan<<<1, 1024>>>(hcount);
    k_hist<<<NHIST, INDIM>>>(hloc, htim, hcount, emb_loc, emb_tim);

    // history = tanh(histin @ W_attn^T + b_attn): M=4096 N=512 K=288
    sgemm_kernel<0,1><<<dim3(4,32), 256>>>(histin, W_attn, b_attn, hist, NHIST, 2*HDIM, INDIM);
    // gi_f = x @ Wih_f^T + bih_f: M=2048 N=768 K=288
    sgemm_kernel<0,0><<<dim3(6,16), 256>>>(x,  Wih_f, bih_f, gi_f, SEQ, 3*HDIM, INDIM);
    // gi_b = xr[0:1024] @ Wih_b^T + bih_b
    sgemm_kernel<0,0><<<dim3(6,8), 256>>>(xr, Wih_b, bih_b, gi_b, TGT, 3*HDIM, INDIM);

    k_gru<<<16, 384>>>(Whh_f, Whh_b, bhh_f, bhh_b);
    k_build_q<<<TGT, 512>>>();

    // scores = q @ hist^T: M=1024 N=4096 K=512
    sgemm_kernel<0,0><<<dim3(32,8), 256>>>(q, hist, (const float*)nullptr, scores, TGT, NHIST, 2*HDIM);
    k_softmax_rows<<<TGT, 256>>>();
    // ctx = attn @ hist: M=1024 N=512 K=4096 (NN)
    sgemm_kernel<1,0><<<dim3(4,8), 256>>>(scores, hist, (const float*)nullptr, ctx, TGT, 2*HDIM, NHIST);

    k_feat<<<TGT, 256>>>(uid, emb_uid);
    // logits = feat @ Wf^T + bf: M=1024 N=100000 K=1088
    sgemm_kernel<0,0><<<dim3((NLOC+127)/128, 8), 256>>>(feat, Wf, bf, out, TGT, NLOC, FEATD);
    k_logsoftmax<<<TGT, 256>>>(out);
}

// round 12
// speedup vs baseline: 1.9292x; 1.9292x over previous
#include <cuda_runtime.h>
#include <cuda_bf16.h>
#include <math.h>
#include <stdint.h>

#define SEQ   2048
#define NHIST 4096
#define TGT   1024
#define DL    256
#define DT    32
#define DU    64
#define HDIM  256
#define INDIM 288
#define NLOC  100000
#define FEATD 1088
#define KPAD  1152          // 36 K-steps of 32
#define NPADR 100096        // 782 * 128

typedef unsigned long long ull;

// ---------------- static scratch ----------------
__device__ float g_x     [SEQ * INDIM];
__device__ float g_xr    [SEQ * INDIM];
__device__ float g_gi_f  [SEQ * 3 * HDIM];
__device__ float g_gi_b  [TGT * 3 * HDIM];
__device__ float g_hs_f  [SEQ * HDIM];
__device__ float g_hs_b  [SEQ * HDIM];
__device__ float g_histin[NHIST * INDIM];
__device__ float g_hist  [NHIST * 2 * HDIM];
__device__ float g_scores[TGT * NHIST];
__device__ float g_q     [TGT * 2 * HDIM];
__device__ float g_ctx   [TGT * 2 * HDIM];
__device__ int   g_offs  [NHIST];
__device__ __align__(16) __nv_bfloat16 g_featb[TGT * KPAD];
__device__ __align__(16) __nv_bfloat16 g_Wfb  [(size_t)NPADR * KPAD];

// ---------------- helpers ----------------
__device__ __forceinline__ ull pk2(float lo, float hi) {
    ull r; asm("mov.b64 %0, {%1, %2};" : "=l"(r) : "f"(lo), "f"(hi)); return r;
}
__device__ __forceinline__ void unpk(ull v, float &a, float &b) {
    asm("mov.b64 {%0, %1}, %2;" : "=f"(a), "=f"(b) : "l"(v));
}
__device__ __forceinline__ void fma2(ull &c, ull a, ull b) {
    asm("fma.rn.f32x2 %0, %1, %2, %0;" : "+l"(c) : "l"(a), "l"(b));
}
__device__ __forceinline__ void cluster_sync_() {
    asm volatile("barrier.cluster.arrive.aligned;\n\t"
                 "barrier.cluster.wait.aligned;" ::: "memory");
}
__device__ __forceinline__ void st_cluster_f32(float* p, unsigned rank, float v) {
    unsigned a = (unsigned)__cvta_generic_to_shared(p), ra;
    asm volatile("mapa.shared::cluster.u32 %0, %1, %2;" : "=r"(ra) : "r"(a), "r"(rank));
    asm volatile("st.shared::cluster.u32 [%0], %1;" :: "r"(ra), "r"(__float_as_uint(v)) : "memory");
}
__device__ __forceinline__ float sigmoidf_(float x) { return 1.0f / (1.0f + expf(-x)); }

__device__ __forceinline__ void cpa16(uint32_t dst, const void* src) {
    asm volatile("cp.async.cg.shared.global [%0], [%1], 16;" :: "r"(dst), "l"(src) : "memory");
}
#define CP_COMMIT() asm volatile("cp.async.commit_group;" ::: "memory")
#define CP_WAIT(n)  asm volatile("cp.async.wait_group %0;" :: "n"(n) : "memory")

__device__ __forceinline__ void ldsm4(uint32_t* r, uint32_t addr) {
    asm volatile("ldmatrix.sync.aligned.m8n8.x4.shared.b16 {%0,%1,%2,%3}, [%4];"
        : "=r"(r[0]), "=r"(r[1]), "=r"(r[2]), "=r"(r[3]) : "r"(addr));
}
__device__ __forceinline__ void mma16816(float* c, uint32_t a0, uint32_t a1, uint32_t a2, uint32_t a3,
                                         uint32_t b0, uint32_t b1) {
    asm volatile("mma.sync.aligned.m16n8k16.row.col.f32.bf16.bf16.f32 "
        "{%0,%1,%2,%3}, {%4,%5,%6,%7}, {%8,%9}, {%0,%1,%2,%3};"
        : "+f"(c[0]), "+f"(c[1]), "+f"(c[2]), "+f"(c[3])
        : "r"(a0), "r"(a1), "r"(a2), "r"(a3), "r"(b0), "r"(b1));
}

// ---------------- gathers ----------------
__global__ void k_gather(const int* __restrict__ loc, const int* __restrict__ tim,
                         const float* __restrict__ emb_loc, const float* __restrict__ emb_tim) {
    int t = blockIdx.x, c = threadIdx.x;
    float v = (c < DL) ? emb_loc[(size_t)loc[t] * DL + c]
                       : emb_tim[(size_t)tim[t] * DT + (c - DL)];
    g_x [(size_t)t * INDIM + c] = v;
    g_xr[(size_t)(SEQ - 1 - t) * INDIM + c] = v;
}

__global__ __launch_bounds__(1024) void k_scan(const int* __restrict__ counts) {
    __shared__ int s[1024];
    int tid = threadIdx.x;
    int v0 = counts[4*tid], v1 = counts[4*tid+1], v2 = counts[4*tid+2], v3 = counts[4*tid+3];
    int locsum = v0 + v1 + v2 + v3;
    s[tid] = locsum; __syncthreads();
    for (int ofs = 1; ofs < 1024; ofs <<= 1) {
        int t_ = 0; if (tid >= ofs) t_ = s[tid - ofs];
        __syncthreads();
        s[tid] += t_;
        __syncthreads();
    }
    int ex = s[tid] - locsum;
    g_offs[4*tid] = ex;  g_offs[4*tid+1] = ex + v0;
    g_offs[4*tid+2] = ex + v0 + v1;  g_offs[4*tid+3] = ex + v0 + v1 + v2;
}

__global__ void k_hist(const int* __restrict__ hloc, const int* __restrict__ htim,
                       const int* __restrict__ counts,
                       const float* __restrict__ emb_loc, const float* __restrict__ emb_tim) {
    int i = blockIdx.x, c = threadIdx.x;
    int off = g_offs[i], cnt = counts[i];
    float v;
    if (c < DL) {
        float acc = 0.f;
        for (int k = 0; k < cnt; k++) acc += emb_loc[(size_t)hloc[off + k] * DL + c];
        v = acc / (float)cnt;
    } else {
        v = emb_tim[(size_t)htim[off] * DT + (c - DL)];
    }
    g_histin[(size_t)i * INDIM + c] = v;
}

__global__ void k_build_q() {
    int b = blockIdx.x, c = threadIdx.x;
    float v = (c < HDIM) ? g_hs_f[(size_t)(SEQ - TGT + b) * HDIM + c]
                         : g_hs_b[(size_t)(SEQ - TGT + b) * HDIM + (c - HDIM)];
    g_q[(size_t)b * (2*HDIM) + c] = v;
}

// feat -> bf16, K padded to 1152 with zeros
__global__ void k_feat(const int* __restrict__ uid, const float* __restrict__ emb_uid) {
    int b = blockIdx.x; int u = uid[0];
    for (int c = threadIdx.x; c < KPAD; c += blockDim.x) {
        float v = 0.f;
        if (c < 2*HDIM)      v = g_q  [(size_t)b * (2*HDIM) + c];
        else if (c < 4*HDIM) v = g_ctx[(size_t)b * (2*HDIM) + (c - 2*HDIM)];
        else if (c < FEATD)  v = emb_uid[(size_t)u * DU + (c - 4*HDIM)];
        g_featb[(size_t)b * KPAD + c] = __float2bfloat16(v);
    }
}

// Wf -> bf16, padded (NPADR x KPAD)
__global__ __launch_bounds__(256) void k_cvt_wf(const float* __restrict__ Wf) {
    size_t idx = (size_t)blockIdx.x * 256 + threadIdx.x;   // total NPADR*144
    int r  = (int)(idx / 144);
    int c8 = (int)(idx % 144);
    uint4 w = make_uint4(0u, 0u, 0u, 0u);
    if (r < NLOC && c8 < 136) {
        const float4* s = (const float4*)(Wf + (size_t)r * FEATD + c8 * 8);
        float4 a = s[0], b = s[1];
        __nv_bfloat162 p0 = __floats2bfloat162_rn(a.x, a.y);
        __nv_bfloat162 p1 = __floats2bfloat162_rn(a.z, a.w);
        __nv_bfloat162 p2 = __floats2bfloat162_rn(b.x, b.y);
        __nv_bfloat162 p3 = __floats2bfloat162_rn(b.z, b.w);
        w.x = *(uint32_t*)&p0; w.y = *(uint32_t*)&p1;
        w.z = *(uint32_t*)&p2; w.w = *(uint32_t*)&p3;
    }
    *(uint4*)(g_Wfb + (size_t)r * KPAD + c8 * 8) = w;
}

// ---------------- row softmax / log-softmax ----------------
__global__ __launch_bounds__(256) void k_softmax_rows() {
    int row = blockIdx.x, tid = threadIdx.x;
    float* p = g_scores + (size_t)row * NHIST;
    __shared__ float red[256];
    float m = -1e30f;
    for (int i = tid; i < NHIST; i += 256) m = fmaxf(m, p[i]);
    red[tid] = m; __syncthreads();
    for (int s = 128; s > 0; s >>= 1) { if (tid < s) red[tid] = fmaxf(red[tid], red[tid+s]); __syncthreads(); }
    m = red[0]; __syncthreads();
    float sum = 0.f;
    for (int i = tid; i < NHIST; i += 256) { float e = __expf(p[i] - m); p[i] = e; sum += e; }
    red[tid] = sum; __syncthreads();
    for (int s = 128; s > 0; s >>= 1) { if (tid < s) red[tid] += red[tid+s]; __syncthreads(); }
    float inv = 1.f / red[0];
    for (int i = tid; i < NHIST; i += 256) p[i] *= inv;
}

__global__ __launch_bounds__(256) void k_logsoftmax(float* __restrict__ out) {
    int row = blockIdx.x, tid = threadIdx.x;
    float* p = out + (size_t)row * NLOC;
    __shared__ float red[256];
    float m = -1e30f;
    for (int i = tid; i < NLOC; i += 256) m = fmaxf(m, p[i]);
    red[tid] = m; __syncthreads();
    for (int s = 128; s > 0; s >>= 1) { if (tid < s) red[tid] = fmaxf(red[tid], red[tid+s]); __syncthreads(); }
    m = red[0]; __syncthreads();
    float sum = 0.f;
    for (int i = tid; i < NLOC; i += 256) sum += __expf(p[i] - m);
    red[tid] = sum; __syncthreads();
    for (int s = 128; s > 0; s >>= 1) { if (tid < s) red[tid] += red[tid+s]; __syncthreads(); }
    float lse = m + logf(red[0]);
    for (int i = tid; i < NLOC; i += 256) p[i] -= lse;
}

// ---------------- SGEMM (fp32, f32x2) for the small GEMMs ----------------
template<int BL, int ACT>
__global__ __launch_bounds__(256, 1) void sgemm_kernel(
    const float* __restrict__ A, const float* __restrict__ B,
    const float* __restrict__ bias, float* __restrict__ C,
    int M, int N, int K)
{
    __shared__ __align__(16) float As[16][128];
    __shared__ __align__(16) float Bs[16][128];
    const int bm = blockIdx.y * 128, bn = blockIdx.x * 128;
    const int tid = threadIdx.x;
    const int tx = tid & 15, ty = tid >> 4;

    ull acc[8][4];
#pragma unroll
    for (int i = 0; i < 8; i++)
#pragma unroll
        for (int j = 0; j < 4; j++) acc[i][j] = 0ull;

    for (int k0 = 0; k0 < K; k0 += 16) {
#pragma unroll
        for (int l = 0; l < 2; l++) {
            int r = (tid >> 2) + l * 64, kc = (tid & 3) * 4, gr = bm + r;
            float4 v = make_float4(0.f,0.f,0.f,0.f);
            if (gr < M) v = *(const float4*)(A + (size_t)gr * K + k0 + kc);
            As[kc][r]=v.x; As[kc+1][r]=v.y; As[kc+2][r]=v.z; As[kc+3][r]=v.w;
        }
        if (BL == 0) {
#pragma unroll
            for (int l = 0; l < 2; l++) {
                int r = (tid >> 2) + l * 64, kc = (tid & 3) * 4, gr = bn + r;
                float4 v = make_float4(0.f,0.f,0.f,0.f);
                if (gr < N) v = *(const float4*)(B + (size_t)gr * K + k0 + kc);
                Bs[kc][r]=v.x; Bs[kc+1][r]=v.y; Bs[kc+2][r]=v.z; Bs[kc+3][r]=v.w;
            }
        } else {
#pragma unroll
            for (int l = 0; l < 2; l++) {
                int kk = (tid >> 5) + l * 8, c = (tid & 31) * 4, gc = bn + c;
                float4 v = make_float4(0.f,0.f,0.f,0.f);
                if (gc < N) v = *(const float4*)(B + (size_t)(k0 + kk) * N + gc);
                *(float4*)&Bs[kk][c] = v;
            }
        }
        __syncthreads();
#pragma unroll
        for (int kk = 0; kk < 16; kk++) {
            float4 a0 = *(float4*)&As[kk][ty * 8];
            float4 a1 = *(float4*)&As[kk][ty * 8 + 4];
            ulonglong2 bp0 = *(ulonglong2*)&Bs[kk][tx * 8];
            ulonglong2 bp1 = *(ulonglong2*)&Bs[kk][tx * 8 + 4];
            float av[8] = {a0.x,a0.y,a0.z,a0.w,a1.x,a1.y,a1.z,a1.w};
#pragma unroll
            for (int i = 0; i < 8; i++) {
                ull aa = pk2(av[i], av[i]);
                fma2(acc[i][0], aa, bp0.x);
                fma2(acc[i][1], aa, bp0.y);
                fma2(acc[i][2], aa, bp1.x);
                fma2(acc[i][3], aa, bp1.y);
            }
        }
        __syncthreads();
    }
#pragma unroll
    for (int i = 0; i < 8; i++) {
        int gr = bm + ty * 8 + i;
        if (gr >= M) continue;
#pragma unroll
        for (int j = 0; j < 4; j++) {
            int gc = bn + tx * 8 + 2 * j;
            if (gc >= N) continue;
            float v0, v1; unpk(acc[i][j], v0, v1);
            if (bias) { v0 += bias[gc]; v1 += bias[gc + 1]; }
            if (ACT == 1) { v0 = tanhf(v0); v1 = tanhf(v1); }
            *(float2*)(C + (size_t)gr * N + gc) = make_float2(v0, v1);
        }
    }
}

// ---------------- GRU: cluster-of-8, register-resident Whh ----------------
__global__ __launch_bounds__(384, 1) __cluster_dims__(8, 1, 1)
void k_gru(const float* __restrict__ Whh_f, const float* __restrict__ Whh_b,
           const float* __restrict__ bhh_f, const float* __restrict__ bhh_b)
{
    __shared__ __align__(16) float hbuf[2][HDIM];
    __shared__ float gh[96];
    const int tid = threadIdx.x;
    unsigned rank; asm("mov.u32 %0, %%cluster_ctarank;" : "=r"(rank));
    const int dir = blockIdx.x >> 3;

    const float* Whh = dir ? Whh_b : Whh_f;
    const float* bhh = dir ? bhh_b : bhh_f;
    const float* gi  = dir ? g_gi_b : g_gi_f;
    float*       hs  = dir ? g_hs_b : g_hs_f;
    const int nsteps = dir ? TGT : SEQ;

    const int rg = tid >> 4, cg = tid & 15;

    ull w2[4][8];
#pragma unroll
    for (int rr = 0; rr < 4; rr++) {
        int lr = 4 * rg + rr;
        int R = (lr >> 5) * HDIM + (int)rank * 32 + (lr & 31);
        const float4* p = (const float4*)(Whh + (size_t)R * HDIM + cg * 16);
#pragma unroll
        for (int q = 0; q < 4; q++) {
            float4 v = p[q];
            w2[rr][2*q]   = pk2(v.x, v.y);
            w2[rr][2*q+1] = pk2(v.z, v.w);
        }
    }
    float bhr = 0.f, bhz = 0.f, bhn = 0.f;
    if (tid < 32) {
        int d = (int)rank * 32 + tid;
        bhr = bhh[d]; bhz = bhh[HDIM + d]; bhn = bhh[2*HDIM + d];
    }
    if (tid < HDIM) { hbuf[0][tid] = 0.f; }
    __syncthreads();
    cluster_sync_();

    int buf = 0;
    for (int t = 0; t < nsteps; t++) {
        float gir = 0.f, giz = 0.f, gin = 0.f;
        if (tid < 32) {
            size_t base = (size_t)t * (3 * HDIM) + rank * 32 + tid;
            gir = gi[base]; giz = gi[base + HDIM]; gin = gi[base + 2*HDIM];
        }
        const float* hb = hbuf[buf];
        ulonglong2 h01 = *(const ulonglong2*)(hb + cg * 16);
        ulonglong2 h23 = *(const ulonglong2*)(hb + cg * 16 + 4);
        ulonglong2 h45 = *(const ulonglong2*)(hb + cg * 16 + 8);
        ulonglong2 h67 = *(const ulonglong2*)(hb + cg * 16 + 12);
        ull hv[8] = {h01.x, h01.y, h23.x, h23.y, h45.x, h45.y, h67.x, h67.y};

        ull acc[4] = {0ull, 0ull, 0ull, 0ull};
#pragma unroll
        for (int rr = 0; rr < 4; rr++)
#pragma unroll
            for (int q = 0; q < 8; q++) fma2(acc[rr], w2[rr][q], hv[q]);

        float accf[4];
#pragma unroll
        for (int rr = 0; rr < 4; rr++) {
            float lo, hi; unpk(acc[rr], lo, hi);
            accf[rr] = lo + hi;
#pragma unroll
            for (int ofs = 8; ofs > 0; ofs >>= 1)
                accf[rr] += __shfl_xor_sync(0xffffffffu, accf[rr], ofs, 16);
        }
        if (cg == 0) {
#pragma unroll
            for (int rr = 0; rr < 4; rr++) gh[4 * rg + rr] = accf[rr];
        }
        __syncthreads();

        if (tid < 32) {
            float hprev = hbuf[buf][(int)rank * 32 + tid];
            float r = sigmoidf_(gir + gh[tid]       + bhr);
            float z = sigmoidf_(giz + gh[32 + tid]  + bhz);
            float n = tanhf    (gin + r * (gh[64 + tid] + bhn));
            float hn = (1.0f - z) * n + z * hprev;
            int d = (int)rank * 32 + tid;
#pragma unroll
            for (unsigned rk = 0; rk < 8; rk++)
                st_cluster_f32(&hbuf[buf ^ 1][d], rk, hn);
            size_t row = dir ? (size_t)(SEQ - 1 - t) : (size_t)t;
            hs[row * HDIM + d] = hn;
        }
        cluster_sync_();
        buf ^= 1;
    }
}

// ---------------- big GEMM: HMMA bf16, out = feat @ Wf^T + bf ----------------
// 128x128x32 tiles, 8 warps (2m x 4n), warp tile 64x32, cp.async double buffer.
// smem rows padded to 80 B -> conflict-free ldmatrix.
#define HM_BUF 20480   // A(10240) + B(10240) per stage

__global__ __launch_bounds__(256) void k_hmma(const float* __restrict__ bf,
                                              float* __restrict__ out)
{
    __shared__ __align__(16) char smem[2 * HM_BUF];
    const int tid = threadIdx.x;
    const int wid = tid >> 5, lane = tid & 31;
    const int wm = wid & 1, wn = wid >> 1;          // 2 x 4 warp grid
    const int m_base = blockIdx.x * 128;            // 8 m-tiles
    const int n_base = blockIdx.y * 128;            // 782 n-tiles

    const uint32_t sbase = (uint32_t)__cvta_generic_to_shared(smem);

    float acc[4][4][4];
#pragma unroll
    for (int i = 0; i < 4; i++)
#pragma unroll
        for (int j = 0; j < 4; j++)
#pragma unroll
            for (int k = 0; k < 4; k++) acc[i][j][k] = 0.f;

    const char* Agbase = (const char*)g_featb + (size_t)m_base * (KPAD * 2);
    const char* Bgbase = (const char*)g_Wfb  + (size_t)n_base * (KPAD * 2);

    auto load_tile = [&](int ks, int stage) {
        const char* Ag = Agbase + ks * 64;
        const char* Bg = Bgbase + ks * 64;
        uint32_t sA = sbase + stage * HM_BUF;
        uint32_t sB = sA + 10240;
#pragma unroll
        for (int i = 0; i < 2; i++) {
            int idx = tid + i * 256;          // 0..511
            int r = idx >> 2, c = idx & 3;
            cpa16(sA + r * 80 + c * 16, Ag + (size_t)r * (KPAD * 2) + c * 16);
            cpa16(sB + r * 80 + c * 16, Bg + (size_t)r * (KPAD * 2) + c * 16);
        }
        CP_COMMIT();
    };

    load_tile(0, 0);

    for (int ks = 0; ks < 36; ks++) {
        int stage = ks & 1;
        if (ks + 1 < 36) { load_tile(ks + 1, stage ^ 1); CP_WAIT(1); }
        else             { CP_WAIT(0); }
        __syncthreads();

        uint32_t sA = sbase + stage * HM_BUF;
        uint32_t sB = sA + 10240;
#pragma unroll
        for (int kk = 0; kk < 2; kk++) {
            uint32_t a[4][4], b[2][4];
#pragma unroll
            for (int mi = 0; mi < 4; mi++)
                ldsm4(a[mi], sA + (uint32_t)((wm * 64 + mi * 16 + (lane & 15)) * 80
                                             + kk * 32 + (lane >> 4) * 16));
#pragma unroll
            for (int nj = 0; nj < 2; nj++)
                ldsm4(b[nj], sB + (uint32_t)((wn * 32 + nj * 16 + (lane & 7) + ((lane >> 4) & 1) * 8) * 80
                                             + kk * 32 + ((lane >> 3) & 1) * 16));
#pragma unroll
            for (int mi = 0; mi < 4; mi++)
#pragma unroll
                for (int ni = 0; ni < 4; ni++)
                    mma16816(acc[mi][ni], a[mi][0], a[mi][1], a[mi][2], a[mi][3],
                             b[ni >> 1][(ni & 1) * 2], b[ni >> 1][(ni & 1) * 2 + 1]);
        }
        __syncthreads();
    }

    // epilogue: c0,c1 -> row (lane>>2), cols (lane&3)*2,+1 ; c2,c3 -> row+8
    const int row_in = lane >> 2, col_in = (lane & 3) * 2;
#pragma unroll
    for (int ni = 0; ni < 4; ni++) {
        int gn = n_base + wn * 32 + ni * 8 + col_in;
        if (gn >= NLOC) continue;
        float bx = bf[gn], by = bf[gn + 1];
#pragma unroll
        for (int mi = 0; mi < 4; mi++) {
#pragma unroll
            for (int h = 0; h < 2; h++) {
                int gm = m_base + wm * 64 + mi * 16 + row_in + h * 8;
                float2 v;
                v.x = acc[mi][ni][h * 2]     + bx;
                v.y = acc[mi][ni][h * 2 + 1] + by;
                *(float2*)(out + (size_t)gm * NLOC + gn) = v;
            }
        }
    }
}

// ---------------- launch ----------------
extern "C" void kernel_launch(void* const* d_in, const int* in_sizes, int n_in,
                              void* d_out, int out_size) {
    const int*   loc     = (const int*)  d_in[0];
    const int*   tim     = (const int*)  d_in[1];
    const int*   hloc    = (const int*)  d_in[2];
    const int*   htim    = (const int*)  d_in[3];
    const int*   hcount  = (const int*)  d_in[4];
    const int*   uid     = (const int*)  d_in[5];
    const float* emb_loc = (const float*)d_in[7];
    const float* emb_tim = (const float*)d_in[8];
    const float* emb_uid = (const float*)d_in[9];
    const float* W_attn  = (const float*)d_in[10];
    const float* b_attn  = (const float*)d_in[11];
    const float* Wih_f   = (const float*)d_in[12];
    const float* Whh_f   = (const float*)d_in[13];
    const float* bih_f   = (const float*)d_in[14];
    const float* bhh_f   = (const float*)d_in[15];
    const float* Wih_b   = (const float*)d_in[16];
    const float* Whh_b   = (const float*)d_in[17];
    const float* bih_b   = (const float*)d_in[18];
    const float* bhh_b   = (const float*)d_in[19];
    const float* Wf      = (const float*)d_in[20];
    const float* bf      = (const float*)d_in[21];
    float* out = (float*)d_out;

    float *x, *xr, *gi_f, *gi_b, *histin, *hist, *scores, *q, *ctx;
    cudaGetSymbolAddress((void**)&x, g_x);
    cudaGetSymbolAddress((void**)&xr, g_xr);
    cudaGetSymbolAddress((void**)&gi_f, g_gi_f);
    cudaGetSymbolAddress((void**)&gi_b, g_gi_b);
    cudaGetSymbolAddress((void**)&histin, g_histin);
    cudaGetSymbolAddress((void**)&hist, g_hist);
    cudaGetSymbolAddress((void**)&scores, g_scores);
    cudaGetSymbolAddress((void**)&q, g_q);
    cudaGetSymbolAddress((void**)&ctx, g_ctx);

    // Wf -> bf16 (independent of everything else; runs first)
    k_cvt_wf<<<(unsigned)(((size_t)NPADR * 144) / 256), 256>>>(Wf);

    k_gather<<<SEQ, INDIM>>>(loc, tim, emb_loc, emb_tim);
    k_scan<<<1, 1024>>>(hcount);
    k_hist<<<NHIST, INDIM>>>(hloc, htim, hcount, emb_loc, emb_tim);

    sgemm_kernel<0,1><<<dim3(4,32), 256>>>(histin, W_attn, b_attn, hist, NHIST, 2*HDIM, INDIM);
    sgemm_kernel<0,0><<<dim3(6,16), 256>>>(x,  Wih_f, bih_f, gi_f, SEQ, 3*HDIM, INDIM);
    sgemm_kernel<0,0><<<dim3(6,8), 256>>>(xr, Wih_b, bih_b, gi_b, TGT, 3*HDIM, INDIM);

    k_gru<<<16, 384>>>(Whh_f, Whh_b, bhh_f, bhh_b);
    k_build_q<<<TGT, 512>>>();

    sgemm_kernel<0,0><<<dim3(32,8), 256>>>(q, hist, (const float*)nullptr, scores, TGT, NHIST, 2*HDIM);
    k_softmax_rows<<<TGT, 256>>>();
    sgemm_kernel<1,0><<<dim3(4,8), 256>>>(scores, hist, (const float*)nullptr, ctx, TGT, 2*HDIM, NHIST);

    k_feat<<<TGT, 256>>>(uid, emb_uid);

    k_hmma<<<dim3(8, 782), 256>>>(bf, out);
    k_logsoftmax<<<TGT, 256>>>(out);
}

// round 13
// speedup vs baseline: 1.9340x; 1.0025x over previous
#include <cuda_runtime.h>
#include <cuda_bf16.h>
#include <math.h>
#include <stdint.h>

#define SEQ   2048
#define NHIST 4096
#define TGT   1024
#define DL    256
#define DT    32
#define DU    64
#define HDIM  256
#define INDIM 288
#define NLOC  100000
#define FEATD 1088
#define KPAD  1152          // 36 K-steps of 32
#define NPADR 100096        // 782 * 128

typedef unsigned long long ull;

// ---------------- static scratch ----------------
__device__ float g_x     [SEQ * INDIM];
__device__ float g_xr    [SEQ * INDIM];
__device__ float g_gi_f  [SEQ * 3 * HDIM];
__device__ float g_gi_b  [TGT * 3 * HDIM];
__device__ float g_hs_f  [SEQ * HDIM];
__device__ float g_hs_b  [SEQ * HDIM];
__device__ float g_histin[NHIST * INDIM];
__device__ float g_hist  [NHIST * 2 * HDIM];
__device__ float g_scores[TGT * NHIST];
__device__ float g_q     [TGT * 2 * HDIM];
__device__ float g_ctx   [TGT * 2 * HDIM];
__device__ int   g_offs  [NHIST];
__device__ __align__(16) __nv_bfloat16 g_featb[TGT * KPAD];
__device__ __align__(16) __nv_bfloat16 g_Wfb  [(size_t)NPADR * KPAD];

// ---------------- helpers ----------------
__device__ __forceinline__ ull pk2(float lo, float hi) {
    ull r; asm("mov.b64 %0, {%1, %2};" : "=l"(r) : "f"(lo), "f"(hi)); return r;
}
__device__ __forceinline__ void unpk(ull v, float &a, float &b) {
    asm("mov.b64 {%0, %1}, %2;" : "=f"(a), "=f"(b) : "l"(v));
}
__device__ __forceinline__ void fma2(ull &c, ull a, ull b) {
    asm("fma.rn.f32x2 %0, %1, %2, %0;" : "+l"(c) : "l"(a), "l"(b));
}
__device__ __forceinline__ void cluster_sync_() {
    asm volatile("barrier.cluster.arrive.aligned;\n\t"
                 "barrier.cluster.wait.aligned;" ::: "memory");
}
__device__ __forceinline__ void st_cluster_f32(float* p, unsigned rank, float v) {
    unsigned a = (unsigned)__cvta_generic_to_shared(p), ra;
    asm volatile("mapa.shared::cluster.u32 %0, %1, %2;" : "=r"(ra) : "r"(a), "r"(rank));
    asm volatile("st.shared::cluster.u32 [%0], %1;" :: "r"(ra), "r"(__float_as_uint(v)) : "memory");
}
__device__ __forceinline__ float sigmoidf_(float x) { return 1.0f / (1.0f + expf(-x)); }

__device__ __forceinline__ void cpa16(uint32_t dst, const void* src) {
    asm volatile("cp.async.cg.shared.global [%0], [%1], 16;" :: "r"(dst), "l"(src) : "memory");
}
#define CP_COMMIT() asm volatile("cp.async.commit_group;" ::: "memory")
#define CP_WAIT(n)  asm volatile("cp.async.wait_group %0;" :: "n"(n) : "memory")

__device__ __forceinline__ void ldsm4(uint32_t* r, uint32_t addr) {
    asm volatile("ldmatrix.sync.aligned.m8n8.x4.shared.b16 {%0,%1,%2,%3}, [%4];"
        : "=r"(r[0]), "=r"(r[1]), "=r"(r[2]), "=r"(r[3]) : "r"(addr));
}
__device__ __forceinline__ void mma16816(float* c, uint32_t a0, uint32_t a1, uint32_t a2, uint32_t a3,
                                         uint32_t b0, uint32_t b1) {
    asm volatile("mma.sync.aligned.m16n8k16.row.col.f32.bf16.bf16.f32 "
        "{%0,%1,%2,%3}, {%4,%5,%6,%7}, {%8,%9}, {%0,%1,%2,%3};"
        : "+f"(c[0]), "+f"(c[1]), "+f"(c[2]), "+f"(c[3])
        : "r"(a0), "r"(a1), "r"(a2), "r"(a3), "r"(b0), "r"(b1));
}

// ---------------- gathers ----------------
__global__ void k_gather(const int* __restrict__ loc, const int* __restrict__ tim,
                         const float* __restrict__ emb_loc, const float* __restrict__ emb_tim) {
    int t = blockIdx.x, c = threadIdx.x;
    float v = (c < DL) ? emb_loc[(size_t)loc[t] * DL + c]
                       : emb_tim[(size_t)tim[t] * DT + (c - DL)];
    g_x [(size_t)t * INDIM + c] = v;
    g_xr[(size_t)(SEQ - 1 - t) * INDIM + c] = v;
}

__global__ __launch_bounds__(1024) void k_scan(const int* __restrict__ counts) {
    __shared__ int s[1024];
    int tid = threadIdx.x;
    int v0 = counts[4*tid], v1 = counts[4*tid+1], v2 = counts[4*tid+2], v3 = counts[4*tid+3];
    int locsum = v0 + v1 + v2 + v3;
    s[tid] = locsum; __syncthreads();
    for (int ofs = 1; ofs < 1024; ofs <<= 1) {
        int t_ = 0; if (tid >= ofs) t_ = s[tid - ofs];
        __syncthreads();
        s[tid] += t_;
        __syncthreads();
    }
    int ex = s[tid] - locsum;
    g_offs[4*tid] = ex;  g_offs[4*tid+1] = ex + v0;
    g_offs[4*tid+2] = ex + v0 + v1;  g_offs[4*tid+3] = ex + v0 + v1 + v2;
}

__global__ void k_hist(const int* __restrict__ hloc, const int* __restrict__ htim,
                       const int* __restrict__ counts,
                       const float* __restrict__ emb_loc, const float* __restrict__ emb_tim) {
    int i = blockIdx.x, c = threadIdx.x;
    int off = g_offs[i], cnt = counts[i];
    float v;
    if (c < DL) {
        float acc = 0.f;
        for (int k = 0; k < cnt; k++) acc += emb_loc[(size_t)hloc[off + k] * DL + c];
        v = acc / (float)cnt;
    } else {
        v = emb_tim[(size_t)htim[off] * DT + (c - DL)];
    }
    g_histin[(size_t)i * INDIM + c] = v;
}

__global__ void k_build_q() {
    int b = blockIdx.x, c = threadIdx.x;
    float v = (c < HDIM) ? g_hs_f[(size_t)(SEQ - TGT + b) * HDIM + c]
                         : g_hs_b[(size_t)(SEQ - TGT + b) * HDIM + (c - HDIM)];
    g_q[(size_t)b * (2*HDIM) + c] = v;
}

// feat -> bf16, K padded to 1152 with zeros
__global__ void k_feat(const int* __restrict__ uid, const float* __restrict__ emb_uid) {
    int b = blockIdx.x; int u = uid[0];
    for (int c = threadIdx.x; c < KPAD; c += blockDim.x) {
        float v = 0.f;
        if (c < 2*HDIM)      v = g_q  [(size_t)b * (2*HDIM) + c];
        else if (c < 4*HDIM) v = g_ctx[(size_t)b * (2*HDIM) + (c - 2*HDIM)];
        else if (c < FEATD)  v = emb_uid[(size_t)u * DU + (c - 4*HDIM)];
        g_featb[(size_t)b * KPAD + c] = __float2bfloat16(v);
    }
}

// Wf -> bf16, padded (NPADR x KPAD)
__global__ __launch_bounds__(256) void k_cvt_wf(const float* __restrict__ Wf) {
    size_t idx = (size_t)blockIdx.x * 256 + threadIdx.x;   // total NPADR*144
    int r  = (int)(idx / 144);
    int c8 = (int)(idx % 144);
    uint4 w = make_uint4(0u, 0u, 0u, 0u);
    if (r < NLOC && c8 < 136) {
        const float4* s = (const float4*)(Wf + (size_t)r * FEATD + c8 * 8);
        float4 a = s[0], b = s[1];
        __nv_bfloat162 p0 = __floats2bfloat162_rn(a.x, a.y);
        __nv_bfloat162 p1 = __floats2bfloat162_rn(a.z, a.w);
        __nv_bfloat162 p2 = __floats2bfloat162_rn(b.x, b.y);
        __nv_bfloat162 p3 = __floats2bfloat162_rn(b.z, b.w);
        w.x = *(uint32_t*)&p0; w.y = *(uint32_t*)&p1;
        w.z = *(uint32_t*)&p2; w.w = *(uint32_t*)&p3;
    }
    *(uint4*)(g_Wfb + (size_t)r * KPAD + c8 * 8) = w;
}

// ---------------- row softmax / log-softmax ----------------
__global__ __launch_bounds__(256) void k_softmax_rows() {
    int row = blockIdx.x, tid = threadIdx.x;
    float* p = g_scores + (size_t)row * NHIST;
    __shared__ float red[256];
    float m = -1e30f;
    for (int i = tid; i < NHIST; i += 256) m = fmaxf(m, p[i]);
    red[tid] = m; __syncthreads();
    for (int s = 128; s > 0; s >>= 1) { if (tid < s) red[tid] = fmaxf(red[tid], red[tid+s]); __syncthreads(); }
    m = red[0]; __syncthreads();
    float sum = 0.f;
    for (int i = tid; i < NHIST; i += 256) { float e = __expf(p[i] - m); p[i] = e; sum += e; }
    red[tid] = sum; __syncthreads();
    for (int s = 128; s > 0; s >>= 1) { if (tid < s) red[tid] += red[tid+s]; __syncthreads(); }
    float inv = 1.f / red[0];
    for (int i = tid; i < NHIST; i += 256) p[i] *= inv;
}

__global__ __launch_bounds__(256) void k_logsoftmax(float* __restrict__ out) {
    int row = blockIdx.x, tid = threadIdx.x;
    float* p = out + (size_t)row * NLOC;
    __shared__ float red[256];
    float m = -1e30f;
    for (int i = tid; i < NLOC; i += 256) m = fmaxf(m, p[i]);
    red[tid] = m; __syncthreads();
    for (int s = 128; s > 0; s >>= 1) { if (tid < s) red[tid] = fmaxf(red[tid], red[tid+s]); __syncthreads(); }
    m = red[0]; __syncthreads();
    float sum = 0.f;
    for (int i = tid; i < NLOC; i += 256) sum += __expf(p[i] - m);
    red[tid] = sum; __syncthreads();
    for (int s = 128; s > 0; s >>= 1) { if (tid < s) red[tid] += red[tid+s]; __syncthreads(); }
    float lse = m + logf(red[0]);
    for (int i = tid; i < NLOC; i += 256) p[i] -= lse;
}

// ---------------- SGEMM (fp32, f32x2) for the small GEMMs ----------------
template<int BL, int ACT>
__global__ __launch_bounds__(256, 1) void sgemm_kernel(
    const float* __restrict__ A, const float* __restrict__ B,
    const float* __restrict__ bias, float* __restrict__ C,
    int M, int N, int K)
{
    __shared__ __align__(16) float As[16][128];
    __shared__ __align__(16) float Bs[16][128];
    const int bm = blockIdx.y * 128, bn = blockIdx.x * 128;
    const int tid = threadIdx.x;
    const int tx = tid & 15, ty = tid >> 4;

    ull acc[8][4];
#pragma unroll
    for (int i = 0; i < 8; i++)
#pragma unroll
        for (int j = 0; j < 4; j++) acc[i][j] = 0ull;

    for (int k0 = 0; k0 < K; k0 += 16) {
#pragma unroll
        for (int l = 0; l < 2; l++) {
            int r = (tid >> 2) + l * 64, kc = (tid & 3) * 4, gr = bm + r;
            float4 v = make_float4(0.f,0.f,0.f,0.f);
            if (gr < M) v = *(const float4*)(A + (size_t)gr * K + k0 + kc);
            As[kc][r]=v.x; As[kc+1][r]=v.y; As[kc+2][r]=v.z; As[kc+3][r]=v.w;
        }
        if (BL == 0) {
#pragma unroll
            for (int l = 0; l < 2; l++) {
                int r = (tid >> 2) + l * 64, kc = (tid & 3) * 4, gr = bn + r;
                float4 v = make_float4(0.f,0.f,0.f,0.f);
                if (gr < N) v = *(const float4*)(B + (size_t)gr * K + k0 + kc);
                Bs[kc][r]=v.x; Bs[kc+1][r]=v.y; Bs[kc+2][r]=v.z; Bs[kc+3][r]=v.w;
            }
        } else {
#pragma unroll
            for (int l = 0; l < 2; l++) {
                int kk = (tid >> 5) + l * 8, c = (tid & 31) * 4, gc = bn + c;
                float4 v = make_float4(0.f,0.f,0.f,0.f);
                if (gc < N) v = *(const float4*)(B + (size_t)(k0 + kk) * N + gc);
                *(float4*)&Bs[kk][c] = v;
            }
        }
        __syncthreads();
#pragma unroll
        for (int kk = 0; kk < 16; kk++) {
            float4 a0 = *(float4*)&As[kk][ty * 8];
            float4 a1 = *(float4*)&As[kk][ty * 8 + 4];
            ulonglong2 bp0 = *(ulonglong2*)&Bs[kk][tx * 8];
            ulonglong2 bp1 = *(ulonglong2*)&Bs[kk][tx * 8 + 4];
            float av[8] = {a0.x,a0.y,a0.z,a0.w,a1.x,a1.y,a1.z,a1.w};
#pragma unroll
            for (int i = 0; i < 8; i++) {
                ull aa = pk2(av[i], av[i]);
                fma2(acc[i][0], aa, bp0.x);
                fma2(acc[i][1], aa, bp0.y);
                fma2(acc[i][2], aa, bp1.x);
                fma2(acc[i][3], aa, bp1.y);
            }
        }
        __syncthreads();
    }
#pragma unroll
    for (int i = 0; i < 8; i++) {
        int gr = bm + ty * 8 + i;
        if (gr >= M) continue;
#pragma unroll
        for (int j = 0; j < 4; j++) {
            int gc = bn + tx * 8 + 2 * j;
            if (gc >= N) continue;
            float v0, v1; unpk(acc[i][j], v0, v1);
            if (bias) { v0 += bias[gc]; v1 += bias[gc + 1]; }
            if (ACT == 1) { v0 = tanhf(v0); v1 = tanhf(v1); }
            *(float2*)(C + (size_t)gr * N + gc) = make_float2(v0, v1);
        }
    }
}

// ---------------- GRU: cluster-of-8, register-resident Whh ----------------
__global__ __launch_bounds__(384, 1) __cluster_dims__(8, 1, 1)
void k_gru(const float* __restrict__ Whh_f, const float* __restrict__ Whh_b,
           const float* __restrict__ bhh_f, const float* __restrict__ bhh_b)
{
    __shared__ __align__(16) float hbuf[2][HDIM];
    __shared__ float gh[96];
    const int tid = threadIdx.x;
    unsigned rank; asm("mov.u32 %0, %%cluster_ctarank;" : "=r"(rank));
    const int dir = blockIdx.x >> 3;

    const float* Whh = dir ? Whh_b : Whh_f;
    const float* bhh = dir ? bhh_b : bhh_f;
    const float* gi  = dir ? g_gi_b : g_gi_f;
    float*       hs  = dir ? g_hs_b : g_hs_f;
    const int nsteps = dir ? TGT : SEQ;

    const int rg = tid >> 4, cg = tid & 15;

    ull w2[4][8];
#pragma unroll
    for (int rr = 0; rr < 4; rr++) {
        int lr = 4 * rg + rr;
        int R = (lr >> 5) * HDIM + (int)rank * 32 + (lr & 31);
        const float4* p = (const float4*)(Whh + (size_t)R * HDIM + cg * 16);
#pragma unroll
        for (int q = 0; q < 4; q++) {
            float4 v = p[q];
            w2[rr][2*q]   = pk2(v.x, v.y);
            w2[rr][2*q+1] = pk2(v.z, v.w);
        }
    }
    float bhr = 0.f, bhz = 0.f, bhn = 0.f;
    if (tid < 32) {
        int d = (int)rank * 32 + tid;
        bhr = bhh[d]; bhz = bhh[HDIM + d]; bhn = bhh[2*HDIM + d];
    }
    if (tid < HDIM) { hbuf[0][tid] = 0.f; }
    __syncthreads();
    cluster_sync_();

    int buf = 0;
    for (int t = 0; t < nsteps; t++) {
        float gir = 0.f, giz = 0.f, gin = 0.f;
        if (tid < 32) {
            size_t base = (size_t)t * (3 * HDIM) + rank * 32 + tid;
            gir = gi[base]; giz = gi[base + HDIM]; gin = gi[base + 2*HDIM];
        }
        const float* hb = hbuf[buf];
        ulonglong2 h01 = *(const ulonglong2*)(hb + cg * 16);
        ulonglong2 h23 = *(const ulonglong2*)(hb + cg * 16 + 4);
        ulonglong2 h45 = *(const ulonglong2*)(hb + cg * 16 + 8);
        ulonglong2 h67 = *(const ulonglong2*)(hb + cg * 16 + 12);
        ull hv[8] = {h01.x, h01.y, h23.x, h23.y, h45.x, h45.y, h67.x, h67.y};

        ull acc[4] = {0ull, 0ull, 0ull, 0ull};
#pragma unroll
        for (int rr = 0; rr < 4; rr++)
#pragma unroll
            for (int q = 0; q < 8; q++) fma2(acc[rr], w2[rr][q], hv[q]);

        float accf[4];
#pragma unroll
        for (int rr = 0; rr < 4; rr++) {
            float lo, hi; unpk(acc[rr], lo, hi);
            accf[rr] = lo + hi;
#pragma unroll
            for (int ofs = 8; ofs > 0; ofs >>= 1)
                accf[rr] += __shfl_xor_sync(0xffffffffu, accf[rr], ofs, 16);
        }
        if (cg == 0) {
#pragma unroll
            for (int rr = 0; rr < 4; rr++) gh[4 * rg + rr] = accf[rr];
        }
        __syncthreads();

        if (tid < 32) {
            float hprev = hbuf[buf][(int)rank * 32 + tid];
            float r = sigmoidf_(gir + gh[tid]       + bhr);
            float z = sigmoidf_(giz + gh[32 + tid]  + bhz);
            float n = tanhf    (gin + r * (gh[64 + tid] + bhn));
            float hn = (1.0f - z) * n + z * hprev;
            int d = (int)rank * 32 + tid;
#pragma unroll
            for (unsigned rk = 0; rk < 8; rk++)
                st_cluster_f32(&hbuf[buf ^ 1][d], rk, hn);
            size_t row = dir ? (size_t)(SEQ - 1 - t) : (size_t)t;
            hs[row * HDIM + d] = hn;
        }
        cluster_sync_();
        buf ^= 1;
    }
}

// ---------------- big GEMM: HMMA bf16, out = feat @ Wf^T + bf ----------------
// 128x128x32 tiles, 8 warps (2m x 4n), warp tile 64x32, cp.async double buffer.
// smem rows padded to 80 B -> conflict-free ldmatrix.
#define HM_BUF 20480   // A(10240) + B(10240) per stage

__global__ __launch_bounds__(256) void k_hmma(const float* __restrict__ bf,
                                              float* __restrict__ out)
{
    __shared__ __align__(16) char smem[2 * HM_BUF];
    const int tid = threadIdx.x;
    const int wid = tid >> 5, lane = tid & 31;
    const int wm = wid & 1, wn = wid >> 1;          // 2 x 4 warp grid
    const int m_base = blockIdx.x * 128;            // 8 m-tiles
    const int n_base = blockIdx.y * 128;            // 782 n-tiles

    const uint32_t sbase = (uint32_t)__cvta_generic_to_shared(smem);

    float acc[4][4][4];
#pragma unroll
    for (int i = 0; i < 4; i++)
#pragma unroll
        for (int j = 0; j < 4; j++)
#pragma unroll
            for (int k = 0; k < 4; k++) acc[i][j][k] = 0.f;

    const char* Agbase = (const char*)g_featb + (size_t)m_base * (KPAD * 2);
    const char* Bgbase = (const char*)g_Wfb  + (size_t)n_base * (KPAD * 2);

    auto load_tile = [&](int ks, int stage) {
        const char* Ag = Agbase + ks * 64;
        const char* Bg = Bgbase + ks * 64;
        uint32_t sA = sbase + stage * HM_BUF;
        uint32_t sB = sA + 10240;
#pragma unroll
        for (int i = 0; i < 2; i++) {
            int idx = tid + i * 256;          // 0..511
            int r = idx >> 2, c = idx & 3;
            cpa16(sA + r * 80 + c * 16, Ag + (size_t)r * (KPAD * 2) + c * 16);
            cpa16(sB + r * 80 + c * 16, Bg + (size_t)r * (KPAD * 2) + c * 16);
        }
        CP_COMMIT();
    };

    load_tile(0, 0);

    for (int ks = 0; ks < 36; ks++) {
        int stage = ks & 1;
        if (ks + 1 < 36) { load_tile(ks + 1, stage ^ 1); CP_WAIT(1); }
        else             { CP_WAIT(0); }
        __syncthreads();

        uint32_t sA = sbase + stage * HM_BUF;
        uint32_t sB = sA + 10240;
#pragma unroll
        for (int kk = 0; kk < 2; kk++) {
            uint32_t a[4][4], b[2][4];
#pragma unroll
            for (int mi = 0; mi < 4; mi++)
                ldsm4(a[mi], sA + (uint32_t)((wm * 64 + mi * 16 + (lane & 15)) * 80
                                             + kk * 32 + (lane >> 4) * 16));
#pragma unroll
            for (int nj = 0; nj < 2; nj++)
                ldsm4(b[nj], sB + (uint32_t)((wn * 32 + nj * 16 + (lane & 7) + ((lane >> 4) & 1) * 8) * 80
                                             + kk * 32 + ((lane >> 3) & 1) * 16));
#pragma unroll
            for (int mi = 0; mi < 4; mi++)
#pragma unroll
                for (int ni = 0; ni < 4; ni++)
                    mma16816(acc[mi][ni], a[mi][0], a[mi][1], a[mi][2], a[mi][3],
                             b[ni >> 1][(ni & 1) * 2], b[ni >> 1][(ni & 1) * 2 + 1]);
        }
        __syncthreads();
    }

    // epilogue: c0,c1 -> row (lane>>2), cols (lane&3)*2,+1 ; c2,c3 -> row+8
    const int row_in = lane >> 2, col_in = (lane & 3) * 2;
#pragma unroll
    for (int ni = 0; ni < 4; ni++) {
        int gn = n_base + wn * 32 + ni * 8 + col_in;
        if (gn >= NLOC) continue;
        float bx = bf[gn], by = bf[gn + 1];
#pragma unroll
        for (int mi = 0; mi < 4; mi++) {
#pragma unroll
            for (int h = 0; h < 2; h++) {
                int gm = m_base + wm * 64 + mi * 16 + row_in + h * 8;
                float2 v;
                v.x = acc[mi][ni][h * 2]     + bx;
                v.y = acc[mi][ni][h * 2 + 1] + by;
                *(float2*)(out + (size_t)gm * NLOC + gn) = v;
            }
        }
    }
}

// ---------------- launch ----------------
extern "C" void kernel_launch(void* const* d_in, const int* in_sizes, int n_in,
                              void* d_out, int out_size) {
    const int*   loc     = (const int*)  d_in[0];
    const int*   tim     = (const int*)  d_in[1];
    const int*   hloc    = (const int*)  d_in[2];
    const int*   htim    = (const int*)  d_in[3];
    const int*   hcount  = (const int*)  d_in[4];
    const int*   uid     = (const int*)  d_in[5];
    const float* emb_loc = (const float*)d_in[7];
    const float* emb_tim = (const float*)d_in[8];
    const float* emb_uid = (const float*)d_in[9];
    const float* W_attn  = (const float*)d_in[10];
    const float* b_attn  = (const float*)d_in[11];
    const float* Wih_f   = (const float*)d_in[12];
    const float* Whh_f   = (const float*)d_in[13];
    const float* bih_f   = (const float*)d_in[14];
    const float* bhh_f   = (const float*)d_in[15];
    const float* Wih_b   = (const float*)d_in[16];
    const float* Whh_b   = (const float*)d_in[17];
    const float* bih_b   = (const float*)d_in[18];
    const float* bhh_b   = (const float*)d_in[19];
    const float* Wf      = (const float*)d_in[20];
    const float* bf      = (const float*)d_in[21];
    float* out = (float*)d_out;

    float *x, *xr, *gi_f, *gi_b, *histin, *hist, *scores, *q, *ctx;
    cudaGetSymbolAddress((void**)&x, g_x);
    cudaGetSymbolAddress((void**)&xr, g_xr);
    cudaGetSymbolAddress((void**)&gi_f, g_gi_f);
    cudaGetSymbolAddress((void**)&gi_b, g_gi_b);
    cudaGetSymbolAddress((void**)&histin, g_histin);
    cudaGetSymbolAddress((void**)&hist, g_hist);
    cudaGetSymbolAddress((void**)&scores, g_scores);
    cudaGetSymbolAddress((void**)&q, g_q);
    cudaGetSymbolAddress((void**)&ctx, g_ctx);

    // Wf -> bf16 (independent of everything else; runs first)
    k_cvt_wf<<<(unsigned)(((size_t)NPADR * 144) / 256), 256>>>(Wf);

    k_gather<<<SEQ, INDIM>>>(loc, tim, emb_loc, emb_tim);
    k_scan<<<1, 1024>>>(hcount);
    k_hist<<<NHIST, INDIM>>>(hloc, htim, hcount, emb_loc, emb_tim);

    sgemm_kernel<0,1><<<dim3(4,32), 256>>>(histin, W_attn, b_attn, hist, NHIST, 2*HDIM, INDIM);
    sgemm_kernel<0,0><<<dim3(6,16), 256>>>(x,  Wih_f, bih_f, gi_f, SEQ, 3*HDIM, INDIM);
    sgemm_kernel<0,0><<<dim3(6,8), 256>>>(xr, Wih_b, bih_b, gi_b, TGT, 3*HDIM, INDIM);

    k_gru<<<16, 384>>>(Whh_f, Whh_b, bhh_f, bhh_b);
    k_build_q<<<TGT, 512>>>();

    sgemm_kernel<0,0><<<dim3(32,8), 256>>>(q, hist, (const float*)nullptr, scores, TGT, NHIST, 2*HDIM);
    k_softmax_rows<<<TGT, 256>>>();
    sgemm_kernel<1,0><<<dim3(4,8), 256>>>(scores, hist, (const float*)nullptr, ctx, TGT, 2*HDIM, NHIST);

    k_feat<<<TGT, 256>>>(uid, emb_uid);

    k_hmma<<<dim3(8, 782), 256>>>(bf, out);
    k_logsoftmax<<<TGT, 256>>>(out);
}